// round 12
// baseline (speedup 1.0000x reference)
#include <cuda_runtime.h>
#include <math.h>

#define BB 4
#define NN 512
#define DD 128
#define TAU_INV 2.0f
#define EPSF 1e-9f

#define TI 16            // i rows per k_main block
#define JS 2             // j splits
#define JR (NN/JS)       // 256 j's per block
#define TJ 32            // j tile staged in shared

// GEMM tiles
#define PBM 32
#define PBN 64
#define PBK 32
#define APAD 2

// ---------------- scratch ----------------
__device__ float g_pj[BB * NN * DD];          // proj = ES@Wp + bp  (1 MB)
__device__ float g_sj[BB * NN * DD];          // proj@W1_src
__device__ float g_ti[BB * NN * DD];          // proj@W1_tgt + b1

// ---------------- packed f32x2 helpers ----------------
__device__ __forceinline__ void fma2acc(unsigned long long& acc,
                                        unsigned long long a, unsigned long long b) {
    asm("fma.rn.f32x2 %0, %1, %2, %0;" : "+l"(acc) : "l"(a), "l"(b));
}
__device__ __forceinline__ unsigned long long bcast2(float a) {
    unsigned long long r;
    asm("mov.b64 %0, {%1, %1};" : "=l"(r) : "f"(a));
    return r;
}
__device__ __forceinline__ float2 unpack2(unsigned long long v) {
    float2 r;
    asm("mov.b64 {%0, %1}, %2;" : "=f"(r.x), "=f"(r.y) : "l"(v));
    return r;
}
// acc += a * relu(s + t), 4 lanes (2 b64 packs)
__device__ __forceinline__ void relu_mad4(unsigned long long& acc0, unsigned long long& acc1,
                                          unsigned long long s0, unsigned long long s1,
                                          unsigned long long t0, unsigned long long t1,
                                          unsigned long long a2)
{
    asm("{\n\t"
        ".reg .b64 x0, x1;\n\t"
        ".reg .f32 l0, h0, l1, h1;\n\t"
        "add.rn.f32x2 x0, %2, %4;\n\t"
        "add.rn.f32x2 x1, %3, %5;\n\t"
        "mov.b64 {l0, h0}, x0;\n\t"
        "mov.b64 {l1, h1}, x1;\n\t"
        "max.f32 l0, l0, 0f00000000;\n\t"
        "max.f32 h0, h0, 0f00000000;\n\t"
        "max.f32 l1, l1, 0f00000000;\n\t"
        "max.f32 h1, h1, 0f00000000;\n\t"
        "mov.b64 x0, {l0, h0};\n\t"
        "mov.b64 x1, {l1, h1};\n\t"
        "fma.rn.f32x2 %0, x0, %6, %0;\n\t"
        "fma.rn.f32x2 %1, x1, %6, %1;\n\t"
        "}"
        : "+l"(acc0), "+l"(acc1)
        : "l"(s0), "l"(s1), "l"(t0), "l"(t1), "l"(a2));
}

// ============ K1a: proj = ES @ Wp + bp;  by==0 blocks also init out_state ============
// grid (2048/32, 128/64) = (64,2); 32x64 tiles.
__global__ void __launch_bounds__(256) k_proj1(const float* __restrict__ ES,
                                               const float* __restrict__ Wp,
                                               const float* __restrict__ bp,
                                               const float* __restrict__ b2,
                                               float* __restrict__ out_state)
{
    __shared__ float sE[PBK][PBM + APAD];   // transposed: sE[k][row]
    __shared__ float sW[PBK][PBN];

    int tid = threadIdx.x;
    int tx  = tid & 15;
    int ty  = tid >> 4;
    int r0  = blockIdx.x * PBM;
    int c0  = blockIdx.y * PBN;

    int lrow = tid >> 3;
    int lk4  = tid & 7;
    int wk   = tid >> 4;
    int wc4  = tid & 15;

    float4 eA, wB[2];
    {
        eA    = *(const float4*)&ES[(size_t)(r0 + lrow) * DD + lk4 * 4];
        wB[0] = *(const float4*)&Wp[(size_t)(wk     ) * DD + c0 + wc4 * 4];
        wB[1] = *(const float4*)&Wp[(size_t)(wk + 16) * DD + c0 + wc4 * 4];
    }

    unsigned long long acc[2][2];
    acc[0][0] = acc[0][1] = acc[1][0] = acc[1][1] = 0ull;

    for (int kt = 0; kt < DD; kt += PBK) {
        if (kt) __syncthreads();
        sE[lk4 * 4 + 0][lrow] = eA.x;
        sE[lk4 * 4 + 1][lrow] = eA.y;
        sE[lk4 * 4 + 2][lrow] = eA.z;
        sE[lk4 * 4 + 3][lrow] = eA.w;
        *(float4*)&sW[wk][wc4 * 4]      = wB[0];
        *(float4*)&sW[wk + 16][wc4 * 4] = wB[1];
        __syncthreads();

        if (kt + PBK < DD) {
            int kn = kt + PBK;
            eA    = *(const float4*)&ES[(size_t)(r0 + lrow) * DD + kn + lk4 * 4];
            wB[0] = *(const float4*)&Wp[(size_t)(kn + wk     ) * DD + c0 + wc4 * 4];
            wB[1] = *(const float4*)&Wp[(size_t)(kn + wk + 16) * DD + c0 + wc4 * 4];
        }

        #pragma unroll 8
        for (int k = 0; k < PBK; k++) {
            float2 e2 = *(const float2*)&sE[k][ty * 2];
            ulonglong2 w2 = *(const ulonglong2*)&sW[k][tx * 4];
            unsigned long long e0 = bcast2(e2.x);
            unsigned long long e1 = bcast2(e2.y);
            fma2acc(acc[0][0], e0, w2.x); fma2acc(acc[0][1], e0, w2.y);
            fma2acc(acc[1][0], e1, w2.x); fma2acc(acc[1][1], e1, w2.y);
        }
    }

    float4 bias = *(const float4*)&bp[c0 + tx * 4];
    #pragma unroll
    for (int r = 0; r < 2; r++) {
        int row = r0 + ty * 2 + r;
        float2 p0 = unpack2(acc[r][0]);
        float2 p1 = unpack2(acc[r][1]);
        float4 o;
        o.x = p0.x + bias.x; o.y = p0.y + bias.y;
        o.z = p1.x + bias.z; o.w = p1.y + bias.w;
        *(float4*)&g_pj[(size_t)row * DD + c0 + tx * 4] = o;
    }

    // init out_state = ES + b2 for this block's 32 rows
    if (blockIdx.y == 0) {
        #pragma unroll
        for (int q = 0; q < 4; q++) {
            int idx = tid + q * 256;
            int row = r0 + (idx >> 5);
            int c4  = idx & 31;
            float4 es = *(const float4*)&ES[(size_t)row * DD + c4 * 4];
            float4 bb = *(const float4*)&b2[c4 * 4];
            float4 o;
            o.x = es.x + bb.x; o.y = es.y + bb.y;
            o.z = es.z + bb.z; o.w = es.w + bb.w;
            *(float4*)&out_state[(size_t)row * DD + c4 * 4] = o;
        }
    }
}

// ============ K1b: [s|t] = proj @ [W1s|W1t] (+b1 on t half) ============
// grid (2048/32, 256/64) = (64,4). Col block c0: <128 -> W1 rows 0..127 (src),
// >=128 -> W1 rows 128..255 (tgt).
__global__ void __launch_bounds__(256) k_proj2(const float* __restrict__ W1,
                                               const float* __restrict__ b1)
{
    __shared__ float sE[PBK][PBM + APAD];
    __shared__ float sW[PBK][PBN];

    int tid = threadIdx.x;
    int tx  = tid & 15;
    int ty  = tid >> 4;
    int r0  = blockIdx.x * PBM;
    int c0  = blockIdx.y * PBN;

    int lrow = tid >> 3;
    int lk4  = tid & 7;
    int wk   = tid >> 4;
    int wc4  = tid & 15;

    int tgt = (c0 >= DD);
    const float* W1b = W1 + (size_t)(tgt ? DD * DD : 0) + (c0 & (DD - 1));

    float4 eA, wB[2];
    {
        eA    = *(const float4*)&g_pj[(size_t)(r0 + lrow) * DD + lk4 * 4];
        wB[0] = *(const float4*)&W1b[(size_t)(wk     ) * DD + wc4 * 4];
        wB[1] = *(const float4*)&W1b[(size_t)(wk + 16) * DD + wc4 * 4];
    }

    unsigned long long acc[2][2];
    acc[0][0] = acc[0][1] = acc[1][0] = acc[1][1] = 0ull;

    for (int kt = 0; kt < DD; kt += PBK) {
        if (kt) __syncthreads();
        sE[lk4 * 4 + 0][lrow] = eA.x;
        sE[lk4 * 4 + 1][lrow] = eA.y;
        sE[lk4 * 4 + 2][lrow] = eA.z;
        sE[lk4 * 4 + 3][lrow] = eA.w;
        *(float4*)&sW[wk][wc4 * 4]      = wB[0];
        *(float4*)&sW[wk + 16][wc4 * 4] = wB[1];
        __syncthreads();

        if (kt + PBK < DD) {
            int kn = kt + PBK;
            eA    = *(const float4*)&g_pj[(size_t)(r0 + lrow) * DD + kn + lk4 * 4];
            wB[0] = *(const float4*)&W1b[(size_t)(kn + wk     ) * DD + wc4 * 4];
            wB[1] = *(const float4*)&W1b[(size_t)(kn + wk + 16) * DD + wc4 * 4];
        }

        #pragma unroll 8
        for (int k = 0; k < PBK; k++) {
            float2 e2 = *(const float2*)&sE[k][ty * 2];
            ulonglong2 w2 = *(const ulonglong2*)&sW[k][tx * 4];
            unsigned long long e0 = bcast2(e2.x);
            unsigned long long e1 = bcast2(e2.y);
            fma2acc(acc[0][0], e0, w2.x); fma2acc(acc[0][1], e0, w2.y);
            fma2acc(acc[1][0], e1, w2.x); fma2acc(acc[1][1], e1, w2.y);
        }
    }

    int mc = c0 & (DD - 1);
    float4 bias;
    if (tgt) bias = *(const float4*)&b1[mc + tx * 4];
    else     bias = make_float4(0.f, 0.f, 0.f, 0.f);
    float* dst = tgt ? g_ti : g_sj;
    #pragma unroll
    for (int r = 0; r < 2; r++) {
        int row = r0 + ty * 2 + r;
        float2 p0 = unpack2(acc[r][0]);
        float2 p1 = unpack2(acc[r][1]);
        float4 o;
        o.x = p0.x + bias.x; o.y = p0.y + bias.y;
        o.z = p1.x + bias.z; o.w = p1.y + bias.w;
        *(float4*)&dst[(size_t)row * DD + mc + tx * 4] = o;
    }
}

// ============ K2: fused softmax + aggregation + partial epilogue (atomics) ============
// grid (32, 4, 2), 256 threads  (Round-10 winner, unchanged)
__global__ void __launch_bounds__(256, 4) k_main(const float* __restrict__ EL,
                                                 const float* __restrict__ UN,
                                                 const float* __restrict__ W2,
                                                 float* __restrict__ out_A,
                                                 float* __restrict__ out_state)
{
    __shared__ float sA[TI * JR];    // 16 KB
    __shared__ float sS[TJ * DD];    // 16 KB; overlaid by sV (8 KB) in phase C

    int tid = threadIdx.x;
    int b   = blockIdx.y;
    int i0  = blockIdx.x * TI;
    int js  = blockIdx.z;

    // -------- phase A: gumbel-softmax rows i0..i0+15, keep js half --------
    {
        int warp = tid >> 5, lane = tid & 31;
        #pragma unroll
        for (int rr = 0; rr < 2; rr++) {
            int r = warp * 2 + rr;
            int i = i0 + r;
            const float* elp = EL + (size_t)i * NN;
            const float* up  = UN + (size_t)i * NN;
            float xv[16];
            float mx = -1e30f;
            #pragma unroll
            for (int c = 0; c < 16; c++) {
                int j = c * 32 + lane;
                float inner = logf(up[j] + EPSF);
                float g = -__logf(-inner + EPSF);
                float x = (elp[j] + g) * TAU_INV;
                xv[c] = x;
                mx = fmaxf(mx, x);
            }
            #pragma unroll
            for (int o = 16; o > 0; o >>= 1) mx = fmaxf(mx, __shfl_xor_sync(0xffffffffu, mx, o));
            float s = 0.f;
            #pragma unroll
            for (int c = 0; c < 16; c++) { float e = __expf(xv[c] - mx); xv[c] = e; s += e; }
            #pragma unroll
            for (int o = 16; o > 0; o >>= 1) s += __shfl_xor_sync(0xffffffffu, s, o);
            float rinv = 1.0f / s;
            float* oA = out_A + ((size_t)b * NN + i) * NN;
            #pragma unroll
            for (int c = 0; c < 16; c++) {
                float a = xv[c] * rinv;
                if ((c >> 3) == js) sA[r * JR + (c & 7) * 32 + lane] = a;
                if (js == 0) oA[c * 32 + lane] = a;
            }
        }
    }
    __syncthreads();

    // -------- phase B --------
    int kq = tid & 31;
    int ig = tid >> 5;
    int iA = ig * 2, iB = ig * 2 + 1;

    ulonglong2 tA = *(const ulonglong2*)&g_ti[((size_t)(b * NN + i0 + iA)) * DD + kq * 4];
    ulonglong2 tB = *(const ulonglong2*)&g_ti[((size_t)(b * NN + i0 + iB)) * DD + kq * 4];
    unsigned long long accA0 = 0ull, accA1 = 0ull, accB0 = 0ull, accB1 = 0ull;

    const float4* sb4 = (const float4*)(g_sj + ((size_t)b * NN + js * JR) * DD);

    #pragma unroll 1
    for (int t = 0; t < JR / TJ; t++) {
        #pragma unroll
        for (int q = 0; q < 4; q++)
            ((float4*)sS)[tid + q * 256] = sb4[t * (TJ * DD / 4) + tid + q * 256];
        __syncthreads();

        const float* arA = sA + iA * JR + t * TJ;
        const float* arB = sA + iB * JR + t * TJ;

        #pragma unroll 4
        for (int jj = 0; jj < TJ; jj += 2) {
            float2 avA = *(const float2*)(arA + jj);
            float2 avB = *(const float2*)(arB + jj);
            {
                ulonglong2 sv = *(const ulonglong2*)&sS[jj * DD + kq * 4];
                unsigned long long aA = bcast2(avA.x);
                unsigned long long aB = bcast2(avB.x);
                relu_mad4(accA0, accA1, sv.x, sv.y, tA.x, tA.y, aA);
                relu_mad4(accB0, accB1, sv.x, sv.y, tB.x, tB.y, aB);
            }
            {
                ulonglong2 sv = *(const ulonglong2*)&sS[(jj + 1) * DD + kq * 4];
                unsigned long long aA = bcast2(avA.y);
                unsigned long long aB = bcast2(avB.y);
                relu_mad4(accA0, accA1, sv.x, sv.y, tA.x, tA.y, aA);
                relu_mad4(accB0, accB1, sv.x, sv.y, tB.x, tB.y, aB);
            }
        }
        __syncthreads();
    }

    // -------- phase C: out += v_partial @ W2 (atomic) --------
    float* sV = sS;
    {
        ulonglong2 oA; oA.x = accA0; oA.y = accA1;
        ulonglong2 oB; oB.x = accB0; oB.y = accB1;
        *(ulonglong2*)&sV[iA * DD + kq * 4] = oA;
        *(ulonglong2*)&sV[iB * DD + kq * 4] = oB;
    }
    __syncthreads();

    {
        int cp = tid & 63;           // col pair
        int rg = tid >> 6;           // 0..3 -> rows rg*4..rg*4+3
        unsigned long long o0 = 0ull, o1 = 0ull, o2 = 0ull, o3 = 0ull;

        #pragma unroll 4
        for (int k = 0; k < DD; k++) {
            unsigned long long w2 = *(const unsigned long long*)&W2[(size_t)k * DD + 2 * cp];
            fma2acc(o0, bcast2(sV[(rg * 4 + 0) * DD + k]), w2);
            fma2acc(o1, bcast2(sV[(rg * 4 + 1) * DD + k]), w2);
            fma2acc(o2, bcast2(sV[(rg * 4 + 2) * DD + k]), w2);
            fma2acc(o3, bcast2(sV[(rg * 4 + 3) * DD + k]), w2);
        }

        size_t base = ((size_t)b * NN + i0 + rg * 4) * DD + 2 * cp;
        float2 q0 = unpack2(o0);
        float2 q1 = unpack2(o1);
        float2 q2 = unpack2(o2);
        float2 q3 = unpack2(o3);
        atomicAdd(&out_state[base + 0 * DD + 0], q0.x);
        atomicAdd(&out_state[base + 0 * DD + 1], q0.y);
        atomicAdd(&out_state[base + 1 * DD + 0], q1.x);
        atomicAdd(&out_state[base + 1 * DD + 1], q1.y);
        atomicAdd(&out_state[base + 2 * DD + 0], q2.x);
        atomicAdd(&out_state[base + 2 * DD + 1], q2.y);
        atomicAdd(&out_state[base + 3 * DD + 0], q3.x);
        atomicAdd(&out_state[base + 3 * DD + 1], q3.y);
    }
}

// ---------------- launch ----------------
extern "C" void kernel_launch(void* const* d_in, const int* in_sizes, int n_in,
                              void* d_out, int out_size)
{
    const float* ES  = (const float*)d_in[0];
    const float* Wp  = (const float*)d_in[1];
    const float* bp  = (const float*)d_in[2];
    const float* EL  = (const float*)d_in[3];
    const float* W1  = (const float*)d_in[4];
    const float* b1  = (const float*)d_in[5];
    const float* W2  = (const float*)d_in[6];
    const float* b2  = (const float*)d_in[7];
    const float* UN  = (const float*)d_in[8];

    float* out_state = (float*)d_out;
    float* out_A     = (float*)d_out + (size_t)BB * NN * DD;

    k_proj1<<<dim3((BB * NN) / PBM, DD / PBN), 256>>>(ES, Wp, bp, b2, out_state);
    k_proj2<<<dim3((BB * NN) / PBM, 256 / PBN), 256>>>(W1, b1);
    k_main<<<dim3(NN / TI, BB, JS), 256>>>(EL, UN, W2, out_A, out_state);
}

// round 15
// speedup vs baseline: 1.4355x; 1.4355x over previous
#include <cuda_runtime.h>
#include <math.h>

#define BB 4
#define NN 512
#define DD 128
#define TAU_INV 2.0f
#define EPSF 1e-9f

#define TI 16            // i rows per k_main block
#define JS 2             // j splits
#define JR (NN/JS)       // 256 j's per block
#define TJ 32            // j tile staged in shared

#define FR 8             // rows per fused-proj block

// ---------------- scratch ----------------
__device__ float g_sj[BB * NN * DD];          // (ES@Wp+bp)@W1_src
__device__ float g_ti[BB * NN * DD];          // (ES@Wp+bp)@W1_tgt + b1

// ---------------- packed f32x2 helpers ----------------
__device__ __forceinline__ void fma2acc(unsigned long long& acc,
                                        unsigned long long a, unsigned long long b) {
    asm("fma.rn.f32x2 %0, %1, %2, %0;" : "+l"(acc) : "l"(a), "l"(b));
}
__device__ __forceinline__ unsigned long long bcast2(float a) {
    unsigned long long r;
    asm("mov.b64 %0, {%1, %1};" : "=l"(r) : "f"(a));
    return r;
}
__device__ __forceinline__ float2 unpack2(unsigned long long v) {
    float2 r;
    asm("mov.b64 {%0, %1}, %2;" : "=f"(r.x), "=f"(r.y) : "l"(v));
    return r;
}
// acc += a * relu(s + t), 4 lanes (2 b64 packs)
__device__ __forceinline__ void relu_mad4(unsigned long long& acc0, unsigned long long& acc1,
                                          unsigned long long s0, unsigned long long s1,
                                          unsigned long long t0, unsigned long long t1,
                                          unsigned long long a2)
{
    asm("{\n\t"
        ".reg .b64 x0, x1;\n\t"
        ".reg .f32 l0, h0, l1, h1;\n\t"
        "add.rn.f32x2 x0, %2, %4;\n\t"
        "add.rn.f32x2 x1, %3, %5;\n\t"
        "mov.b64 {l0, h0}, x0;\n\t"
        "mov.b64 {l1, h1}, x1;\n\t"
        "max.f32 l0, l0, 0f00000000;\n\t"
        "max.f32 h0, h0, 0f00000000;\n\t"
        "max.f32 l1, l1, 0f00000000;\n\t"
        "max.f32 h1, h1, 0f00000000;\n\t"
        "mov.b64 x0, {l0, h0};\n\t"
        "mov.b64 x1, {l1, h1};\n\t"
        "fma.rn.f32x2 %0, x0, %6, %0;\n\t"
        "fma.rn.f32x2 %1, x1, %6, %1;\n\t"
        "}"
        : "+l"(acc0), "+l"(acc1)
        : "l"(s0), "l"(s1), "l"(t0), "l"(t1), "l"(a2));
}

// ============ K1: fused projection chain, one block = 8 rows ============
// grid 2048/8 = 256 blocks, 256 threads, 8 KB smem, 2 syncs total.
//   sE = ES rows; sP = sE@Wp + bp (smem only); [s|t] = sP@W1 (+b1) -> global.
//   Also: out_state = ES + b2 for these rows.
__global__ void __launch_bounds__(256) k_fproj(const float* __restrict__ ES,
                                               const float* __restrict__ Wp,
                                               const float* __restrict__ bp,
                                               const float* __restrict__ W1,
                                               const float* __restrict__ b1,
                                               const float* __restrict__ b2,
                                               float* __restrict__ out_state)
{
    __shared__ float sE[FR * DD];   // 4 KB
    __shared__ float sP[FR * DD];   // 4 KB

    int tid = threadIdx.x;
    int r0  = blockIdx.x * FR;

    // stage ES rows (256 float4)
    ((float4*)sE)[tid] = ((const float4*)(ES + (size_t)r0 * DD))[tid];

    // out_state = ES + b2 for these 8 rows (reuse the same float4)
    {
        int row = r0 + (tid >> 5);
        int c4  = tid & 31;
        float4 es = ((float4*)sE)[tid];
        float4 bb = *(const float4*)&b2[c4 * 4];
        float4 o;
        o.x = es.x + bb.x; o.y = es.y + bb.y;
        o.z = es.z + bb.z; o.w = es.w + bb.w;
        *(float4*)&out_state[(size_t)row * DD + c4 * 4] = o;
    }
    __syncthreads();

    // phase 1: sP = sE @ Wp + bp
    // thread: cp = tid&63 (cols 2cp,2cp+1), rg = tid>>6 (rows rg*2, rg*2+1)
    {
        int cp = tid & 63;
        int rg = tid >> 6;
        unsigned long long acc0 = 0ull, acc1 = 0ull;
        const float* e0 = sE + (rg * 2 + 0) * DD;
        const float* e1 = sE + (rg * 2 + 1) * DD;
        #pragma unroll 8
        for (int k = 0; k < DD; k++) {
            unsigned long long w = *(const unsigned long long*)&Wp[(size_t)k * DD + 2 * cp];
            fma2acc(acc0, bcast2(e0[k]), w);
            fma2acc(acc1, bcast2(e1[k]), w);
        }
        float2 bp2 = *(const float2*)&bp[2 * cp];
        float2 p0 = unpack2(acc0);
        float2 p1 = unpack2(acc1);
        p0.x += bp2.x; p0.y += bp2.y;
        p1.x += bp2.x; p1.y += bp2.y;
        *(float2*)&sP[(rg * 2 + 0) * DD + 2 * cp] = p0;
        *(float2*)&sP[(rg * 2 + 1) * DD + 2 * cp] = p1;
    }
    __syncthreads();

    // phase 2: [s|t] = sP @ W1 (+b1 on t half)
    // thread: h = tid>>7 (0=src,1=tgt), cp = tid&63, rg = (tid>>6)&1 (rows rg*4..rg*4+3)
    {
        int h  = tid >> 7;
        int cp = tid & 63;
        int rg = (tid >> 6) & 1;
        const float* W1b = W1 + (size_t)h * DD * DD;
        const float* p0 = sP + (rg * 4 + 0) * DD;
        const float* p1 = sP + (rg * 4 + 1) * DD;
        const float* p2 = sP + (rg * 4 + 2) * DD;
        const float* p3 = sP + (rg * 4 + 3) * DD;
        unsigned long long a0 = 0ull, a1 = 0ull, a2 = 0ull, a3 = 0ull;
        #pragma unroll 8
        for (int k = 0; k < DD; k++) {
            unsigned long long w = *(const unsigned long long*)&W1b[(size_t)k * DD + 2 * cp];
            fma2acc(a0, bcast2(p0[k]), w);
            fma2acc(a1, bcast2(p1[k]), w);
            fma2acc(a2, bcast2(p2[k]), w);
            fma2acc(a3, bcast2(p3[k]), w);
        }
        float2 bias = make_float2(0.f, 0.f);
        if (h) bias = *(const float2*)&b1[2 * cp];
        float* dst = h ? g_ti : g_sj;
        float2 q0 = unpack2(a0);
        float2 q1 = unpack2(a1);
        float2 q2 = unpack2(a2);
        float2 q3 = unpack2(a3);
        q0.x += bias.x; q0.y += bias.y;
        q1.x += bias.x; q1.y += bias.y;
        q2.x += bias.x; q2.y += bias.y;
        q3.x += bias.x; q3.y += bias.y;
        *(float2*)&dst[(size_t)(r0 + rg * 4 + 0) * DD + 2 * cp] = q0;
        *(float2*)&dst[(size_t)(r0 + rg * 4 + 1) * DD + 2 * cp] = q1;
        *(float2*)&dst[(size_t)(r0 + rg * 4 + 2) * DD + 2 * cp] = q2;
        *(float2*)&dst[(size_t)(r0 + rg * 4 + 3) * DD + 2 * cp] = q3;
    }
}

// ============ K2: fused softmax + aggregation + partial epilogue (atomics) ============
// grid (32, 4, 2), 256 threads  (Round-10 winner, unchanged)
__global__ void __launch_bounds__(256, 4) k_main(const float* __restrict__ EL,
                                                 const float* __restrict__ UN,
                                                 const float* __restrict__ W2,
                                                 float* __restrict__ out_A,
                                                 float* __restrict__ out_state)
{
    __shared__ float sA[TI * JR];    // 16 KB
    __shared__ float sS[TJ * DD];    // 16 KB; overlaid by sV (8 KB) in phase C

    int tid = threadIdx.x;
    int b   = blockIdx.y;
    int i0  = blockIdx.x * TI;
    int js  = blockIdx.z;

    // -------- phase A: gumbel-softmax rows i0..i0+15, keep js half --------
    {
        int warp = tid >> 5, lane = tid & 31;
        #pragma unroll
        for (int rr = 0; rr < 2; rr++) {
            int r = warp * 2 + rr;
            int i = i0 + r;
            const float* elp = EL + (size_t)i * NN;
            const float* up  = UN + (size_t)i * NN;
            float xv[16];
            float mx = -1e30f;
            #pragma unroll
            for (int c = 0; c < 16; c++) {
                int j = c * 32 + lane;
                float inner = logf(up[j] + EPSF);
                float g = -__logf(-inner + EPSF);
                float x = (elp[j] + g) * TAU_INV;
                xv[c] = x;
                mx = fmaxf(mx, x);
            }
            #pragma unroll
            for (int o = 16; o > 0; o >>= 1) mx = fmaxf(mx, __shfl_xor_sync(0xffffffffu, mx, o));
            float s = 0.f;
            #pragma unroll
            for (int c = 0; c < 16; c++) { float e = __expf(xv[c] - mx); xv[c] = e; s += e; }
            #pragma unroll
            for (int o = 16; o > 0; o >>= 1) s += __shfl_xor_sync(0xffffffffu, s, o);
            float rinv = 1.0f / s;
            float* oA = out_A + ((size_t)b * NN + i) * NN;
            #pragma unroll
            for (int c = 0; c < 16; c++) {
                float a = xv[c] * rinv;
                if ((c >> 3) == js) sA[r * JR + (c & 7) * 32 + lane] = a;
                if (js == 0) oA[c * 32 + lane] = a;
            }
        }
    }
    __syncthreads();

    // -------- phase B --------
    int kq = tid & 31;
    int ig = tid >> 5;
    int iA = ig * 2, iB = ig * 2 + 1;

    ulonglong2 tA = *(const ulonglong2*)&g_ti[((size_t)(b * NN + i0 + iA)) * DD + kq * 4];
    ulonglong2 tB = *(const ulonglong2*)&g_ti[((size_t)(b * NN + i0 + iB)) * DD + kq * 4];
    unsigned long long accA0 = 0ull, accA1 = 0ull, accB0 = 0ull, accB1 = 0ull;

    const float4* sb4 = (const float4*)(g_sj + ((size_t)b * NN + js * JR) * DD);

    #pragma unroll 1
    for (int t = 0; t < JR / TJ; t++) {
        #pragma unroll
        for (int q = 0; q < 4; q++)
            ((float4*)sS)[tid + q * 256] = sb4[t * (TJ * DD / 4) + tid + q * 256];
        __syncthreads();

        const float* arA = sA + iA * JR + t * TJ;
        const float* arB = sA + iB * JR + t * TJ;

        #pragma unroll 4
        for (int jj = 0; jj < TJ; jj += 2) {
            float2 avA = *(const float2*)(arA + jj);
            float2 avB = *(const float2*)(arB + jj);
            {
                ulonglong2 sv = *(const ulonglong2*)&sS[jj * DD + kq * 4];
                unsigned long long aA = bcast2(avA.x);
                unsigned long long aB = bcast2(avB.x);
                relu_mad4(accA0, accA1, sv.x, sv.y, tA.x, tA.y, aA);
                relu_mad4(accB0, accB1, sv.x, sv.y, tB.x, tB.y, aB);
            }
            {
                ulonglong2 sv = *(const ulonglong2*)&sS[(jj + 1) * DD + kq * 4];
                unsigned long long aA = bcast2(avA.y);
                unsigned long long aB = bcast2(avB.y);
                relu_mad4(accA0, accA1, sv.x, sv.y, tA.x, tA.y, aA);
                relu_mad4(accB0, accB1, sv.x, sv.y, tB.x, tB.y, aB);
            }
        }
        __syncthreads();
    }

    // -------- phase C: out += v_partial @ W2 (atomic) --------
    float* sV = sS;
    {
        ulonglong2 oA; oA.x = accA0; oA.y = accA1;
        ulonglong2 oB; oB.x = accB0; oB.y = accB1;
        *(ulonglong2*)&sV[iA * DD + kq * 4] = oA;
        *(ulonglong2*)&sV[iB * DD + kq * 4] = oB;
    }
    __syncthreads();

    {
        int cp = tid & 63;           // col pair
        int rg = tid >> 6;           // 0..3 -> rows rg*4..rg*4+3
        unsigned long long o0 = 0ull, o1 = 0ull, o2 = 0ull, o3 = 0ull;

        #pragma unroll 4
        for (int k = 0; k < DD; k++) {
            unsigned long long w2 = *(const unsigned long long*)&W2[(size_t)k * DD + 2 * cp];
            fma2acc(o0, bcast2(sV[(rg * 4 + 0) * DD + k]), w2);
            fma2acc(o1, bcast2(sV[(rg * 4 + 1) * DD + k]), w2);
            fma2acc(o2, bcast2(sV[(rg * 4 + 2) * DD + k]), w2);
            fma2acc(o3, bcast2(sV[(rg * 4 + 3) * DD + k]), w2);
        }

        size_t base = ((size_t)b * NN + i0 + rg * 4) * DD + 2 * cp;
        float2 q0 = unpack2(o0);
        float2 q1 = unpack2(o1);
        float2 q2 = unpack2(o2);
        float2 q3 = unpack2(o3);
        atomicAdd(&out_state[base + 0 * DD + 0], q0.x);
        atomicAdd(&out_state[base + 0 * DD + 1], q0.y);
        atomicAdd(&out_state[base + 1 * DD + 0], q1.x);
        atomicAdd(&out_state[base + 1 * DD + 1], q1.y);
        atomicAdd(&out_state[base + 2 * DD + 0], q2.x);
        atomicAdd(&out_state[base + 2 * DD + 1], q2.y);
        atomicAdd(&out_state[base + 3 * DD + 0], q3.x);
        atomicAdd(&out_state[base + 3 * DD + 1], q3.y);
    }
}

// ---------------- launch ----------------
extern "C" void kernel_launch(void* const* d_in, const int* in_sizes, int n_in,
                              void* d_out, int out_size)
{
    const float* ES  = (const float*)d_in[0];
    const float* Wp  = (const float*)d_in[1];
    const float* bp  = (const float*)d_in[2];
    const float* EL  = (const float*)d_in[3];
    const float* W1  = (const float*)d_in[4];
    const float* b1  = (const float*)d_in[5];
    const float* W2  = (const float*)d_in[6];
    const float* b2  = (const float*)d_in[7];
    const float* UN  = (const float*)d_in[8];

    float* out_state = (float*)d_out;
    float* out_A     = (float*)d_out + (size_t)BB * NN * DD;

    k_fproj<<<(BB * NN) / FR, 256>>>(ES, Wp, bp, W1, b1, b2, out_state);
    k_main<<<dim3(NN / TI, BB, JS), 256>>>(EL, UN, W2, out_A, out_state);
}